// round 4
// baseline (speedup 1.0000x reference)
#include <cuda_runtime.h>
#include <cstdint>

#define BB 64
#define TT 1024
#define KK 256
#define HALF 128
#define SROWS 224          // transT rows cached in backtrace SMEM (224 KB)

// ---------------- scratch ---------------------------------------------------
__device__ float g_state[TT * BB * KK];    // all forward states, 64 MB
__device__ float g_transT[KK * KK];        // transposed transitions

// ---------------- helpers ---------------------------------------------------
__device__ __forceinline__ uint32_t smem_u32(const void* p) {
    return (uint32_t)__cvta_generic_to_shared(p);
}

// monotone float->u32 map: preserves ordering exactly (finite values)
__device__ __forceinline__ unsigned fmono(float f) {
    int b = __float_as_int(f);
    return (unsigned)(b ^ ((b >> 31) | 0x80000000));
}

__device__ __forceinline__ void cluster_sync_all() {
    asm volatile("barrier.cluster.arrive.aligned;" ::: "memory");
    asm volatile("barrier.cluster.wait.aligned;" ::: "memory");
}

__device__ __forceinline__ uint32_t mapa_peer(uint32_t laddr, unsigned peer) {
    uint32_t raddr;
    asm volatile("mapa.shared::cluster.u32 %0, %1, %2;"
                 : "=r"(raddr) : "r"(laddr), "r"(peer));
    return raddr;
}

__device__ __forceinline__ void mbar_init(uint32_t addr, unsigned count) {
    asm volatile("mbarrier.init.shared.b64 [%0], %1;" :: "r"(addr), "r"(count) : "memory");
}
__device__ __forceinline__ void mbar_arrive_remote_release(uint32_t raddr) {
    asm volatile("mbarrier.arrive.release.cluster.shared::cluster.b64 _, [%0];"
                 :: "r"(raddr) : "memory");
}
__device__ __forceinline__ void mbar_wait_cluster(uint32_t addr, unsigned parity) {
    asm volatile(
        "{\n\t"
        ".reg .pred P1;\n\t"
        "WAIT_%=:\n\t"
        "mbarrier.try_wait.parity.acquire.cluster.shared::cta.b64 P1, [%0], %1, 0x989680;\n\t"
        "@P1 bra.uni DONE_%=;\n\t"
        "bra.uni WAIT_%=;\n\t"
        "DONE_%=:\n\t"
        "}"
        :: "r"(addr), "r"(parity) : "memory");
}
__device__ __forceinline__ void st_cluster_b64(uint32_t raddr, float2 v) {
    unsigned long long u;
    memcpy(&u, &v, 8);
    asm volatile("st.shared::cluster.b64 [%0], %1;" :: "r"(raddr), "l"(u) : "memory");
}

// ---------------- transpose kernel ------------------------------------------
__global__ void transpose_kernel(const float* __restrict__ trans)
{
    __shared__ float tile[32][33];
    int bx = blockIdx.x, by = blockIdx.y;
    int x = bx * 32 + threadIdx.x;
    #pragma unroll
    for (int r = 0; r < 4; ++r) {
        int y = by * 32 + threadIdx.y + r * 8;
        tile[threadIdx.y + r * 8][threadIdx.x] = trans[y * KK + x];
    }
    __syncthreads();
    int x2 = by * 32 + threadIdx.x;
    #pragma unroll
    for (int r = 0; r < 4; ++r) {
        int y2 = bx * 32 + threadIdx.y + r * 8;
        g_transT[y2 * KK + x2] = tile[threadIdx.x][threadIdx.y + r * 8];
    }
}

// ---------------- forward kernel (512 threads, values only) -----------------
// 2-CTA cluster per batch. CTA rank owns j columns [rank*128, rank*128+128).
// Thread layout: warp w (16 warps), lane = pr*8 + ig; pr in [0,4), ig in [0,8).
// Thread owns j pair jp = w*4 + pr (j = jp*2, jp*2+1) and i-range
// half*128 + ig*16 + [0,16) per phase. Trans entirely in registers (64 floats).
// Phase A = own-half i (local data), then mbar wait, phase B = peer-half i.
__global__ void __cluster_dims__(2, 1, 1) __launch_bounds__(512, 1)
fwd_kernel(const float* __restrict__ em, const float* __restrict__ trans)
{
    __shared__ float st[2][KK];
    __shared__ __align__(8) unsigned long long mbar;

    const int bid  = blockIdx.x;
    const int b    = bid >> 1;
    const unsigned rank = bid & 1;
    const unsigned peer = rank ^ 1u;
    const int tid  = threadIdx.x;
    const int w    = tid >> 5;
    const int lane = tid & 31;
    const int pr   = lane >> 3;            // pair-group in warp
    const int ig   = lane & 7;             // i-group
    const int jp   = w * 4 + pr;           // 0..63
    const int jg   = rank * HALF + jp * 2; // global j column base (pair)

    const uint32_t mbar_l = smem_u32(&mbar);
    if (tid == 0) mbar_init(mbar_l, 1);

    // transition registers: trA/trB[k] = trans[half*128 + ig*16 + k][jg..jg+1]
    const int iA = rank * HALF + ig * 16;
    const int iB = peer * HALF + ig * 16;
    float2 trA[16], trB[16];
    #pragma unroll
    for (int k = 0; k < 16; ++k)
        trA[k] = *(const float2*)&trans[(iA + k) * KK + jg];
    #pragma unroll
    for (int k = 0; k < 16; ++k)
        trB[k] = *(const float2*)&trans[(iB + k) * KK + jg];

    // initial state = emissions[b,0,:]
    if (tid < KK) {
        float v = em[(b * TT) * KK + tid];
        st[0][tid] = v;
        if (rank == 0) g_state[b * KK + tid] = v;
    }
    __syncthreads();
    cluster_sync_all();          // peer mbar init + st[0] ready on both sides

    // precomputed peer addresses for writer pushes (double buffer)
    const uint32_t peer0 = mapa_peer(smem_u32(&st[0][jg]), peer);
    const uint32_t peer1 = mapa_peer(smem_u32(&st[1][jg]), peer);
    const uint32_t mbar_r = mapa_peer(mbar_l, peer);
    unsigned par = 0;

    const bool writer = (ig == 0);
    float2 emCur = make_float2(0.f, 0.f);
    if (writer)
        emCur = __ldg((const float2*)&em[((b * TT + 1) * KK) + jg]);

    for (int t = 1; t < TT; ++t) {
        const float* cur = st[(t + 1) & 1];
        float*       nxt = st[t & 1];

        // prefetch next step's emission
        float2 emNxt = make_float2(0.f, 0.f);
        if (writer && (t + 1 < TT))
            emNxt = __ldg((const float2*)&em[((b * TT + t + 1) * KK) + jg]);

        // ---- phase A: own-half i (locally produced, no wait) ----
        float a0, a1;
        {
            const float* curA = cur + iA;
            float4 sv = *(const float4*)curA;
            a0 = __fmaf_rn(sv.x, 1.0f, trA[0].x);
            a1 = __fmaf_rn(sv.x, 1.0f, trA[0].y);
            a0 = fmaxf(a0, __fmaf_rn(sv.y, 1.0f, trA[1].x));
            a1 = fmaxf(a1, __fmaf_rn(sv.y, 1.0f, trA[1].y));
            a0 = fmaxf(a0, __fmaf_rn(sv.z, 1.0f, trA[2].x));
            a1 = fmaxf(a1, __fmaf_rn(sv.z, 1.0f, trA[2].y));
            a0 = fmaxf(a0, __fmaf_rn(sv.w, 1.0f, trA[3].x));
            a1 = fmaxf(a1, __fmaf_rn(sv.w, 1.0f, trA[3].y));
            #pragma unroll
            for (int k4 = 1; k4 < 4; ++k4) {
                float4 s = *(const float4*)(curA + k4 * 4);
                a0 = fmaxf(a0, __fmaf_rn(s.x, 1.0f, trA[k4 * 4 + 0].x));
                a1 = fmaxf(a1, __fmaf_rn(s.x, 1.0f, trA[k4 * 4 + 0].y));
                a0 = fmaxf(a0, __fmaf_rn(s.y, 1.0f, trA[k4 * 4 + 1].x));
                a1 = fmaxf(a1, __fmaf_rn(s.y, 1.0f, trA[k4 * 4 + 1].y));
                a0 = fmaxf(a0, __fmaf_rn(s.z, 1.0f, trA[k4 * 4 + 2].x));
                a1 = fmaxf(a1, __fmaf_rn(s.z, 1.0f, trA[k4 * 4 + 2].y));
                a0 = fmaxf(a0, __fmaf_rn(s.w, 1.0f, trA[k4 * 4 + 3].x));
                a1 = fmaxf(a1, __fmaf_rn(s.w, 1.0f, trA[k4 * 4 + 3].y));
            }
        }

        // ---- wait for peer half of state(t-1) (in flight during phase A) ----
        if (t >= 2) {
            mbar_wait_cluster(mbar_l, par);
            par ^= 1u;
        }

        // ---- phase B: peer-half i ----
        {
            const float* curB = cur + iB;
            #pragma unroll
            for (int k4 = 0; k4 < 4; ++k4) {
                float4 s = *(const float4*)(curB + k4 * 4);
                a0 = fmaxf(a0, __fmaf_rn(s.x, 1.0f, trB[k4 * 4 + 0].x));
                a1 = fmaxf(a1, __fmaf_rn(s.x, 1.0f, trB[k4 * 4 + 0].y));
                a0 = fmaxf(a0, __fmaf_rn(s.y, 1.0f, trB[k4 * 4 + 1].x));
                a1 = fmaxf(a1, __fmaf_rn(s.y, 1.0f, trB[k4 * 4 + 1].y));
                a0 = fmaxf(a0, __fmaf_rn(s.z, 1.0f, trB[k4 * 4 + 2].x));
                a1 = fmaxf(a1, __fmaf_rn(s.z, 1.0f, trB[k4 * 4 + 2].y));
                a0 = fmaxf(a0, __fmaf_rn(s.w, 1.0f, trB[k4 * 4 + 3].x));
                a1 = fmaxf(a1, __fmaf_rn(s.w, 1.0f, trB[k4 * 4 + 3].y));
            }
        }

        // butterfly max over the 8 i-groups (lane bits 0..2)
        #pragma unroll
        for (int off = 1; off <= 4; off <<= 1) {
            a0 = fmaxf(a0, __shfl_xor_sync(0xffffffffu, a0, off));
            a1 = fmaxf(a1, __shfl_xor_sync(0xffffffffu, a1, off));
        }

        if (writer) {
            float2 ns = make_float2(a0 + emCur.x, a1 + emCur.y);
            *(float2*)&nxt[jg] = ns;                           // local copy
            st_cluster_b64((t & 1) ? peer1 : peer0, ns);       // peer copy
            *(float2*)&g_state[(t * BB + b) * KK + jg] = ns;   // for backtrace
        }
        emCur = emNxt;

        __syncthreads();                     // all stores issued
        if (tid == 0)
            mbar_arrive_remote_release(mbar_r);   // signal peer: data en route
    }

    cluster_sync_all();   // keep SMEM alive until peer consumed last arrival
}

// ---------------- backtrace: serial argmax recompute along decoded path -----
extern __shared__ float sT[];

__global__ void __launch_bounds__(256, 1) backtrace_kernel(float* __restrict__ out)
{
    const int b   = blockIdx.x;
    const int tid = threadIdx.x;

    for (int idx = tid; idx < SROWS * (KK / 4); idx += 256)
        ((float4*)sT)[idx] = ((const float4*)g_transT)[idx];
    __syncthreads();
    if (tid >= 32) return;
    const int lane = tid;

    // ---- last tag: argmax over state row 1023 (first-index tie-break) ----
    int cur;
    {
        const float4* rp = (const float4*)(g_state + (1023 * BB + b) * KK) + lane * 2;
        float4 sa = __ldg(rp), sb = __ldg(rp + 1);
        unsigned um = fmono(sa.x); int ui = lane * 8;
        unsigned u;
        u = fmono(sa.y); if (u > um) { um = u; ui = lane * 8 + 1; }
        u = fmono(sa.z); if (u > um) { um = u; ui = lane * 8 + 2; }
        u = fmono(sa.w); if (u > um) { um = u; ui = lane * 8 + 3; }
        u = fmono(sb.x); if (u > um) { um = u; ui = lane * 8 + 4; }
        u = fmono(sb.y); if (u > um) { um = u; ui = lane * 8 + 5; }
        u = fmono(sb.z); if (u > um) { um = u; ui = lane * 8 + 6; }
        u = fmono(sb.w); if (u > um) { um = u; ui = lane * 8 + 7; }
        unsigned gmax = __reduce_max_sync(0xffffffffu, um);
        unsigned mask = __ballot_sync(0xffffffffu, um == gmax);
        int lead = __ffs(mask) - 1;
        cur = __shfl_sync(0xffffffffu, ui, lead);
        if (lane == 0) out[b * TT + (TT - 1)] = (float)cur;
    }

    // depth-4 register prefetch of state rows (addresses independent of chain)
    float4 pfa[4], pfb[4];
    #pragma unroll
    for (int d = 0; d < 4; ++d) {
        const float4* rp = (const float4*)(g_state + ((1022 - d) * BB + b) * KK) + lane * 2;
        pfa[d] = __ldg(rp);
        pfb[d] = __ldg(rp + 1);
    }

    for (int t = TT - 1; t >= 1; --t) {
        const int slot = (TT - 1 - t) & 3;
        float4 sa = pfa[slot], sb = pfb[slot];

        int nrow = t - 5;
        if (nrow >= 0) {
            const float4* rp = (const float4*)(g_state + (nrow * BB + b) * KK) + lane * 2;
            pfa[slot] = __ldg(rp);
            pfb[slot] = __ldg(rp + 1);
        }

        const float4* trp = (cur < SROWS)
            ? (const float4*)(sT + cur * KK)
            : (const float4*)(g_transT + cur * KK);
        float4 t0 = trp[lane * 2];
        float4 t1 = trp[lane * 2 + 1];

        unsigned umA = fmono(sa.x + t0.x); int uiA = lane * 8;
        unsigned umB = fmono(sb.x + t1.x); int uiB = lane * 8 + 4;
        unsigned u;
        u = fmono(sa.y + t0.y); if (u > umA) { umA = u; uiA = lane * 8 + 1; }
        u = fmono(sb.y + t1.y); if (u > umB) { umB = u; uiB = lane * 8 + 5; }
        u = fmono(sa.z + t0.z); if (u > umA) { umA = u; uiA = lane * 8 + 2; }
        u = fmono(sb.z + t1.z); if (u > umB) { umB = u; uiB = lane * 8 + 6; }
        u = fmono(sa.w + t0.w); if (u > umA) { umA = u; uiA = lane * 8 + 3; }
        u = fmono(sb.w + t1.w); if (u > umB) { umB = u; uiB = lane * 8 + 7; }
        if (umB > umA) { umA = umB; uiA = uiB; }   // strict >: lower index wins ties

        unsigned gmax = __reduce_max_sync(0xffffffffu, umA);
        unsigned mask = __ballot_sync(0xffffffffu, umA == gmax);
        int lead = __ffs(mask) - 1;
        int prev = __shfl_sync(0xffffffffu, uiA, lead);

        if (lane == 0) out[b * TT + (t - 1)] = (float)prev;
        cur = prev;
    }
}

// ---------------- launch ----------------------------------------------------
extern "C" void kernel_launch(void* const* d_in, const int* in_sizes, int n_in,
                              void* d_out, int out_size)
{
    const float* em    = (const float*)d_in[0];  // [B, T, K] fp32
    const float* trans = (const float*)d_in[1];  // [K, K] fp32
    float* out = (float*)d_out;                  // [B, T] fp32

    const int bt_smem = SROWS * KK * (int)sizeof(float);   // 229376
    cudaFuncSetAttribute(backtrace_kernel,
                         cudaFuncAttributeMaxDynamicSharedMemorySize, bt_smem);

    transpose_kernel<<<dim3(8, 8), dim3(32, 8)>>>(trans);
    fwd_kernel<<<2 * BB, 512>>>(em, trans);
    backtrace_kernel<<<BB, 256, bt_smem>>>(out);
}

// round 5
// speedup vs baseline: 1.0922x; 1.0922x over previous
#include <cuda_runtime.h>
#include <cstdint>

#define BB 64
#define TT 1024
#define KK 256
#define HALF 128
#define SROWS 224          // transT rows cached in backtrace SMEM (224 KB)

// ---------------- scratch ---------------------------------------------------
__device__ float g_state[TT * BB * KK];    // all forward states, 64 MB
__device__ float g_transT[KK * KK];        // transposed transitions

// ---------------- helpers ---------------------------------------------------
__device__ __forceinline__ uint32_t smem_u32(const void* p) {
    return (uint32_t)__cvta_generic_to_shared(p);
}

// monotone float->u32 map: preserves ordering exactly (finite values)
__device__ __forceinline__ unsigned fmono(float f) {
    int b = __float_as_int(f);
    return (unsigned)(b ^ ((b >> 31) | 0x80000000));
}

__device__ __forceinline__ void cluster_sync_all() {
    asm volatile("barrier.cluster.arrive.aligned;" ::: "memory");
    asm volatile("barrier.cluster.wait.aligned;" ::: "memory");
}

__device__ __forceinline__ uint32_t mapa_peer(uint32_t laddr, unsigned peer) {
    uint32_t raddr;
    asm volatile("mapa.shared::cluster.u32 %0, %1, %2;"
                 : "=r"(raddr) : "r"(laddr), "r"(peer));
    return raddr;
}

__device__ __forceinline__ void mbar_init(uint32_t addr, unsigned count) {
    asm volatile("mbarrier.init.shared.b64 [%0], %1;" :: "r"(addr), "r"(count) : "memory");
}
__device__ __forceinline__ void mbar_arrive_remote_release(uint32_t raddr) {
    asm volatile("mbarrier.arrive.release.cluster.shared::cluster.b64 _, [%0];"
                 :: "r"(raddr) : "memory");
}
__device__ __forceinline__ void mbar_wait_cluster(uint32_t addr, unsigned parity) {
    asm volatile(
        "{\n\t"
        ".reg .pred P1;\n\t"
        "WAIT_%=:\n\t"
        "mbarrier.try_wait.parity.acquire.cluster.shared::cta.b64 P1, [%0], %1, 0x989680;\n\t"
        "@P1 bra.uni DONE_%=;\n\t"
        "bra.uni WAIT_%=;\n\t"
        "DONE_%=:\n\t"
        "}"
        :: "r"(addr), "r"(parity) : "memory");
}
__device__ __forceinline__ void st_cluster_b64(uint32_t raddr, float2 v) {
    unsigned long long u;
    memcpy(&u, &v, 8);
    asm volatile("st.shared::cluster.b64 [%0], %1;" :: "r"(raddr), "l"(u) : "memory");
}

// bit-exact add: rn(sv*1.0f + tr) == rn(sv + tr); FFMA-imm form runs at rt 1
__device__ __forceinline__ float addx(float sv, float tr) {
    return __fmaf_rn(sv, 1.0f, tr);
}

__global__ void noop_kernel() {}

// ---------------- transpose kernel ------------------------------------------
__global__ void transpose_kernel(const float* __restrict__ trans)
{
    __shared__ float tile[32][33];
    int bx = blockIdx.x, by = blockIdx.y;
    int x = bx * 32 + threadIdx.x;
    #pragma unroll
    for (int r = 0; r < 4; ++r) {
        int y = by * 32 + threadIdx.y + r * 8;
        tile[threadIdx.y + r * 8][threadIdx.x] = trans[y * KK + x];
    }
    __syncthreads();
    int x2 = by * 32 + threadIdx.x;
    #pragma unroll
    for (int r = 0; r < 4; ++r) {
        int y2 = bx * 32 + threadIdx.y + r * 8;
        g_transT[y2 * KK + x2] = tile[threadIdx.x][threadIdx.y + r * 8];
    }
}

// ---------------- forward kernel (G=2 batches per cluster) ------------------
// 2-CTA cluster handles batches b0,b1. CTA rank owns j in [rank*128,+128).
// Thread layout (R3-proven): warp w, lane = g*4 + q; thread covers j-quad
// jcol = rank*128 + w*16 + q*4 and i = k*8 + g. Trans in registers (128 fl),
// SHARED across both batches. One mbar wait + one remote arrive per step
// covers both batches -> sync cost amortized 2x.
__global__ void __cluster_dims__(2, 1, 1) __launch_bounds__(256, 1)
fwd_kernel(const float* __restrict__ em, const float* __restrict__ trans)
{
    __shared__ float st[2][2][KK];          // [buf][batch][K]
    __shared__ __align__(8) unsigned long long mbar;

    const int bid  = blockIdx.x;
    const int cl   = bid >> 1;
    const int b0   = cl * 2;
    const int b1   = b0 + 1;
    const unsigned rank = bid & 1;
    const unsigned peer = rank ^ 1u;
    const int tid  = threadIdx.x;
    const int w    = tid >> 5;
    const int lane = tid & 31;
    const int q    = lane & 3;
    const int g    = lane >> 2;
    const int jcol = rank * HALF + w * 16 + q * 4;

    const uint32_t mbar_l = smem_u32(&mbar);
    if (tid == 0) mbar_init(mbar_l, 1);

    // transition registers: trA[k] = trans[rank*128 + k*8+g][jcol..+3]
    float4 trA[16], trB[16];
    #pragma unroll
    for (int k = 0; k < 16; ++k)
        trA[k] = *(const float4*)&trans[(rank * HALF + k * 8 + g) * KK + jcol];
    #pragma unroll
    for (int k = 0; k < 16; ++k)
        trB[k] = *(const float4*)&trans[(peer * HALF + k * 8 + g) * KK + jcol];

    // initial state = emissions[b,0,:] for both batches
    {
        float v0 = em[(b0 * TT) * KK + tid];
        float v1 = em[(b1 * TT) * KK + tid];
        st[0][0][tid] = v0;
        st[0][1][tid] = v1;
        if (rank == 0) {
            g_state[b0 * KK + tid] = v0;
            g_state[b1 * KK + tid] = v1;
        }
    }
    __syncthreads();
    cluster_sync_all();          // peer mbar init + st[0] ready on both sides

    const bool writer = (lane < 4);
    const int jW = rank * HALF + w * 16 + lane * 4;   // writer's j-quad
    // peer SMEM addresses for writer pushes: [buf][batch]
    const uint32_t pA00 = mapa_peer(smem_u32(&st[0][0][jW]), peer);
    const uint32_t pA01 = mapa_peer(smem_u32(&st[0][1][jW]), peer);
    const uint32_t pA10 = mapa_peer(smem_u32(&st[1][0][jW]), peer);
    const uint32_t pA11 = mapa_peer(smem_u32(&st[1][1][jW]), peer);
    const uint32_t mbar_r = mapa_peer(mbar_l, peer);
    unsigned par = 0;

    float4 emC0 = make_float4(0.f, 0.f, 0.f, 0.f);
    float4 emC1 = make_float4(0.f, 0.f, 0.f, 0.f);
    if (writer) {
        emC0 = __ldg((const float4*)&em[((b0 * TT + 1) * KK) + jW]);
        emC1 = __ldg((const float4*)&em[((b1 * TT + 1) * KK) + jW]);
    }

    for (int t = 1; t < TT; ++t) {
        const int cb = (t + 1) & 1;
        const int nb = t & 1;
        const float* cur0 = st[cb][0];
        const float* cur1 = st[cb][1];
        float*       nxt0 = st[nb][0];
        float*       nxt1 = st[nb][1];

        // prefetch next step's emissions
        float4 emN0 = make_float4(0.f, 0.f, 0.f, 0.f);
        float4 emN1 = make_float4(0.f, 0.f, 0.f, 0.f);
        if (writer && (t + 1 < TT)) {
            emN0 = __ldg((const float4*)&em[((b0 * TT + t + 1) * KK) + jW]);
            emN1 = __ldg((const float4*)&em[((b1 * TT + t + 1) * KK) + jW]);
        }

        // ---- phase A: own-half i, both batches (local data, no wait) ----
        float a00, a01, a02, a03, a10, a11, a12, a13;
        {
            float s0 = cur0[rank * HALF + g];
            float s1 = cur1[rank * HALF + g];
            a00 = addx(s0, trA[0].x); a01 = addx(s0, trA[0].y);
            a02 = addx(s0, trA[0].z); a03 = addx(s0, trA[0].w);
            a10 = addx(s1, trA[0].x); a11 = addx(s1, trA[0].y);
            a12 = addx(s1, trA[0].z); a13 = addx(s1, trA[0].w);
        }
        #pragma unroll
        for (int k = 1; k < 16; ++k) {
            float s0 = cur0[rank * HALF + k * 8 + g];
            float s1 = cur1[rank * HALF + k * 8 + g];
            a00 = fmaxf(a00, addx(s0, trA[k].x));
            a01 = fmaxf(a01, addx(s0, trA[k].y));
            a02 = fmaxf(a02, addx(s0, trA[k].z));
            a03 = fmaxf(a03, addx(s0, trA[k].w));
            a10 = fmaxf(a10, addx(s1, trA[k].x));
            a11 = fmaxf(a11, addx(s1, trA[k].y));
            a12 = fmaxf(a12, addx(s1, trA[k].z));
            a13 = fmaxf(a13, addx(s1, trA[k].w));
        }

        // ---- wait for peer halves of state(t-1) (in flight during A) ----
        if (t >= 2) {
            mbar_wait_cluster(mbar_l, par);
            par ^= 1u;
        }

        // ---- phase B: peer-half i, both batches ----
        #pragma unroll
        for (int k = 0; k < 16; ++k) {
            float s0 = cur0[peer * HALF + k * 8 + g];
            float s1 = cur1[peer * HALF + k * 8 + g];
            a00 = fmaxf(a00, addx(s0, trB[k].x));
            a01 = fmaxf(a01, addx(s0, trB[k].y));
            a02 = fmaxf(a02, addx(s0, trB[k].z));
            a03 = fmaxf(a03, addx(s0, trB[k].w));
            a10 = fmaxf(a10, addx(s1, trB[k].x));
            a11 = fmaxf(a11, addx(s1, trB[k].y));
            a12 = fmaxf(a12, addx(s1, trB[k].z));
            a13 = fmaxf(a13, addx(s1, trB[k].w));
        }

        // butterfly max over the 8 i-groups (lane bits 2..4)
        #pragma unroll
        for (int off = 4; off <= 16; off <<= 1) {
            a00 = fmaxf(a00, __shfl_xor_sync(0xffffffffu, a00, off));
            a01 = fmaxf(a01, __shfl_xor_sync(0xffffffffu, a01, off));
            a02 = fmaxf(a02, __shfl_xor_sync(0xffffffffu, a02, off));
            a03 = fmaxf(a03, __shfl_xor_sync(0xffffffffu, a03, off));
            a10 = fmaxf(a10, __shfl_xor_sync(0xffffffffu, a10, off));
            a11 = fmaxf(a11, __shfl_xor_sync(0xffffffffu, a11, off));
            a12 = fmaxf(a12, __shfl_xor_sync(0xffffffffu, a12, off));
            a13 = fmaxf(a13, __shfl_xor_sync(0xffffffffu, a13, off));
        }

        if (writer) {
            float4 n0 = make_float4(a00 + emC0.x, a01 + emC0.y,
                                    a02 + emC0.z, a03 + emC0.w);
            float4 n1 = make_float4(a10 + emC1.x, a11 + emC1.y,
                                    a12 + emC1.z, a13 + emC1.w);
            *(float4*)&nxt0[jW] = n0;
            *(float4*)&nxt1[jW] = n1;
            uint32_t p0 = nb ? pA10 : pA00;
            uint32_t p1 = nb ? pA11 : pA01;
            st_cluster_b64(p0,     make_float2(n0.x, n0.y));
            st_cluster_b64(p0 + 8, make_float2(n0.z, n0.w));
            st_cluster_b64(p1,     make_float2(n1.x, n1.y));
            st_cluster_b64(p1 + 8, make_float2(n1.z, n1.w));
            *(float4*)&g_state[(t * BB + b0) * KK + jW] = n0;
            *(float4*)&g_state[(t * BB + b1) * KK + jW] = n1;
        }
        emC0 = emN0;
        emC1 = emN1;

        __syncthreads();                     // all stores issued
        if (tid == 0)
            mbar_arrive_remote_release(mbar_r);   // one signal covers both batches
    }

    cluster_sync_all();   // keep SMEM alive until peer consumed last arrival
}

// ---------------- backtrace: serial argmax recompute along decoded path -----
extern __shared__ float sT[];

__global__ void __launch_bounds__(256, 1) backtrace_kernel(float* __restrict__ out)
{
    const int b   = blockIdx.x;
    const int tid = threadIdx.x;

    for (int idx = tid; idx < SROWS * (KK / 4); idx += 256)
        ((float4*)sT)[idx] = ((const float4*)g_transT)[idx];
    __syncthreads();
    if (tid >= 32) return;
    const int lane = tid;

    // ---- last tag: argmax over state row 1023 (first-index tie-break) ----
    int cur;
    {
        const float4* rp = (const float4*)(g_state + (1023 * BB + b) * KK) + lane * 2;
        float4 sa = __ldg(rp), sb = __ldg(rp + 1);
        unsigned um = fmono(sa.x); int ui = lane * 8;
        unsigned u;
        u = fmono(sa.y); if (u > um) { um = u; ui = lane * 8 + 1; }
        u = fmono(sa.z); if (u > um) { um = u; ui = lane * 8 + 2; }
        u = fmono(sa.w); if (u > um) { um = u; ui = lane * 8 + 3; }
        u = fmono(sb.x); if (u > um) { um = u; ui = lane * 8 + 4; }
        u = fmono(sb.y); if (u > um) { um = u; ui = lane * 8 + 5; }
        u = fmono(sb.z); if (u > um) { um = u; ui = lane * 8 + 6; }
        u = fmono(sb.w); if (u > um) { um = u; ui = lane * 8 + 7; }
        unsigned gmax = __reduce_max_sync(0xffffffffu, um);
        unsigned mask = __ballot_sync(0xffffffffu, um == gmax);
        int lead = __ffs(mask) - 1;
        cur = __shfl_sync(0xffffffffu, ui, lead);
        if (lane == 0) out[b * TT + (TT - 1)] = (float)cur;
    }

    // depth-4 register prefetch of state rows (addresses independent of chain)
    float4 pfa[4], pfb[4];
    #pragma unroll
    for (int d = 0; d < 4; ++d) {
        const float4* rp = (const float4*)(g_state + ((1022 - d) * BB + b) * KK) + lane * 2;
        pfa[d] = __ldg(rp);
        pfb[d] = __ldg(rp + 1);
    }

    for (int t = TT - 1; t >= 1; --t) {
        const int slot = (TT - 1 - t) & 3;
        float4 sa = pfa[slot], sb = pfb[slot];

        int nrow = t - 5;
        if (nrow >= 0) {
            const float4* rp = (const float4*)(g_state + (nrow * BB + b) * KK) + lane * 2;
            pfa[slot] = __ldg(rp);
            pfb[slot] = __ldg(rp + 1);
        }

        const float4* trp = (cur < SROWS)
            ? (const float4*)(sT + cur * KK)
            : (const float4*)(g_transT + cur * KK);
        float4 t0 = trp[lane * 2];
        float4 t1 = trp[lane * 2 + 1];

        unsigned umA = fmono(sa.x + t0.x); int uiA = lane * 8;
        unsigned umB = fmono(sb.x + t1.x); int uiB = lane * 8 + 4;
        unsigned u;
        u = fmono(sa.y + t0.y); if (u > umA) { umA = u; uiA = lane * 8 + 1; }
        u = fmono(sb.y + t1.y); if (u > umB) { umB = u; uiB = lane * 8 + 5; }
        u = fmono(sa.z + t0.z); if (u > umA) { umA = u; uiA = lane * 8 + 2; }
        u = fmono(sb.z + t1.z); if (u > umB) { umB = u; uiB = lane * 8 + 6; }
        u = fmono(sa.w + t0.w); if (u > umA) { umA = u; uiA = lane * 8 + 3; }
        u = fmono(sb.w + t1.w); if (u > umB) { umB = u; uiB = lane * 8 + 7; }
        if (umB > umA) { umA = umB; uiA = uiB; }   // strict >: lower index wins ties

        unsigned gmax = __reduce_max_sync(0xffffffffu, umA);
        unsigned mask = __ballot_sync(0xffffffffu, umA == gmax);
        int lead = __ffs(mask) - 1;
        int prev = __shfl_sync(0xffffffffu, uiA, lead);

        if (lane == 0) out[b * TT + (t - 1)] = (float)prev;
        cur = prev;
    }
}

// ---------------- launch ----------------------------------------------------
extern "C" void kernel_launch(void* const* d_in, const int* in_sizes, int n_in,
                              void* d_out, int out_size)
{
    const float* em    = (const float*)d_in[0];  // [B, T, K] fp32
    const float* trans = (const float*)d_in[1];  // [K, K] fp32
    float* out = (float*)d_out;                  // [B, T] fp32

    const int bt_smem = SROWS * KK * (int)sizeof(float);   // 229376
    cudaFuncSetAttribute(backtrace_kernel,
                         cudaFuncAttributeMaxDynamicSharedMemorySize, bt_smem);

    transpose_kernel<<<dim3(8, 8), dim3(32, 8)>>>(trans);   // launch 1
    noop_kernel<<<1, 32>>>();                               // launch 2
    noop_kernel<<<1, 32>>>();                               // launch 3
    fwd_kernel<<<BB, 256>>>(em, trans);                     // launch 4 <- ncu
    backtrace_kernel<<<BB, 256, bt_smem>>>(out);            // launch 5
}

// round 6
// speedup vs baseline: 1.6536x; 1.5140x over previous
#include <cuda_runtime.h>
#include <cstdint>

#define BB 64
#define TT 1024
#define KK 256
#define HALF 128
#define SROWS 224          // transT rows cached in backtrace SMEM (224 KB)

// ---------------- scratch ---------------------------------------------------
__device__ float g_state[TT * BB * KK];    // all forward states, 64 MB
__device__ float g_transT[KK * KK];        // transposed transitions

// ---------------- helpers ---------------------------------------------------
__device__ __forceinline__ uint32_t smem_u32(const void* p) {
    return (uint32_t)__cvta_generic_to_shared(p);
}

// monotone float->u32 map: preserves ordering exactly (finite values)
__device__ __forceinline__ unsigned fmono(float f) {
    int b = __float_as_int(f);
    return (unsigned)(b ^ ((b >> 31) | 0x80000000));
}

__device__ __forceinline__ void cluster_sync_all() {
    asm volatile("barrier.cluster.arrive.aligned;" ::: "memory");
    asm volatile("barrier.cluster.wait.aligned;" ::: "memory");
}

__device__ __forceinline__ uint32_t mapa_peer(uint32_t laddr, unsigned peer) {
    uint32_t raddr;
    asm volatile("mapa.shared::cluster.u32 %0, %1, %2;"
                 : "=r"(raddr) : "r"(laddr), "r"(peer));
    return raddr;
}

__device__ __forceinline__ void mbar_init(uint32_t addr, unsigned count) {
    asm volatile("mbarrier.init.shared.b64 [%0], %1;" :: "r"(addr), "r"(count) : "memory");
}
// local arrive(1) + expect 'bytes' of incoming async-store traffic this phase
__device__ __forceinline__ void mbar_arrive_expect_tx(uint32_t addr, unsigned bytes) {
    asm volatile("mbarrier.arrive.expect_tx.shared.b64 _, [%0], %1;"
                 :: "r"(addr), "r"(bytes) : "memory");
}
__device__ __forceinline__ void mbar_wait_cluster(uint32_t addr, unsigned parity) {
    asm volatile(
        "{\n\t"
        ".reg .pred P1;\n\t"
        "WAIT_%=:\n\t"
        "mbarrier.try_wait.parity.acquire.cluster.shared::cta.b64 P1, [%0], %1, 0x989680;\n\t"
        "@P1 bra.uni DONE_%=;\n\t"
        "bra.uni WAIT_%=;\n\t"
        "DONE_%=:\n\t"
        "}"
        :: "r"(addr), "r"(parity) : "memory");
}
// one-way async store to peer SMEM; counts 8 bytes on the peer's mbarrier
__device__ __forceinline__ void st_async_b64(uint32_t raddr, float2 v, uint32_t rmbar) {
    unsigned long long u;
    memcpy(&u, &v, 8);
    asm volatile(
        "st.async.weak.shared::cluster.mbarrier::complete_tx::bytes.b64 [%0], %1, [%2];"
        :: "r"(raddr), "l"(u), "r"(rmbar) : "memory");
}

// bit-exact add: rn(sv*1.0f + tr) == rn(sv + tr); FFMA-imm form runs at rt 1
__device__ __forceinline__ float addx(float sv, float tr) {
    return __fmaf_rn(sv, 1.0f, tr);
}

__global__ void noop_kernel() {}

// ---------------- transpose kernel ------------------------------------------
__global__ void transpose_kernel(const float* __restrict__ trans)
{
    __shared__ float tile[32][33];
    int bx = blockIdx.x, by = blockIdx.y;
    int x = bx * 32 + threadIdx.x;
    #pragma unroll
    for (int r = 0; r < 4; ++r) {
        int y = by * 32 + threadIdx.y + r * 8;
        tile[threadIdx.y + r * 8][threadIdx.x] = trans[y * KK + x];
    }
    __syncthreads();
    int x2 = by * 32 + threadIdx.x;
    #pragma unroll
    for (int r = 0; r < 4; ++r) {
        int y2 = bx * 32 + threadIdx.y + r * 8;
        g_transT[y2 * KK + x2] = tile[threadIdx.x][threadIdx.y + r * 8];
    }
}

// ---------------- forward kernel (st.async exchange, values only) -----------
// 2-CTA cluster per batch (R3 layout). CTA rank owns j in [rank*128,+128).
// Warp w, lane = g*4 + q; thread covers j-quad jcol = rank*128+w*16+q*4 and
// i = k*8 + g. Trans in registers. Peer half exchanged via st.async with
// transaction-counting mbarriers: NO release fence, NO store drain at BAR.
__global__ void __cluster_dims__(2, 1, 1) __launch_bounds__(256, 1)
fwd_kernel(const float* __restrict__ em, const float* __restrict__ trans)
{
    __shared__ float st[2][KK];
    __shared__ __align__(8) unsigned long long mb[2];

    const int bid  = blockIdx.x;
    const int b    = bid >> 1;
    const unsigned rank = bid & 1;
    const unsigned peer = rank ^ 1u;
    const int tid  = threadIdx.x;
    const int w    = tid >> 5;
    const int lane = tid & 31;
    const int q    = lane & 3;
    const int g    = lane >> 2;
    const int jcol = rank * HALF + w * 16 + q * 4;

    const uint32_t mb0_l = smem_u32(&mb[0]);
    const uint32_t mb1_l = mb0_l + 8;
    if (tid == 0) { mbar_init(mb0_l, 1); mbar_init(mb1_l, 1); }

    // transition registers
    float4 trA[16], trB[16];
    #pragma unroll
    for (int k = 0; k < 16; ++k)
        trA[k] = *(const float4*)&trans[(rank * HALF + k * 8 + g) * KK + jcol];
    #pragma unroll
    for (int k = 0; k < 16; ++k)
        trB[k] = *(const float4*)&trans[(peer * HALF + k * 8 + g) * KK + jcol];

    // initial state = emissions[b,0,:] (both CTAs load full row locally)
    {
        float v = em[(b * TT) * KK + tid];
        st[0][tid] = v;
        if (rank == 0) g_state[b * KK + tid] = v;
    }
    __syncthreads();
    cluster_sync_all();          // peer mbar init complete before any st.async

    const bool writer = (lane < 4);
    const int jW = rank * HALF + w * 16 + lane * 4;   // writer's j-quad
    const uint32_t pA0 = mapa_peer(smem_u32(&st[0][jW]), peer);
    const uint32_t pA1 = mapa_peer(smem_u32(&st[1][jW]), peer);
    const uint32_t rmb0 = mapa_peer(mb0_l, peer);
    const uint32_t rmb1 = mapa_peer(mb1_l, peer);
    unsigned p0 = 0, p1 = 0;

    float4 emCur = make_float4(0.f, 0.f, 0.f, 0.f);
    if (writer)
        emCur = __ldg((const float4*)&em[((b * TT + 1) * KK) + jW]);

    for (int t = 1; t < TT; ++t) {
        const int nb = t & 1;            // buffer being written (state t)
        const float* cur = st[nb ^ 1];
        float*       nxt = st[nb];

        // announce this phase's expected incoming bytes (local, cheap).
        // Safe: this mbar's previous phase was consumed at step t-1.
        if (tid == 0)
            mbar_arrive_expect_tx(nb ? mb1_l : mb0_l, 512u);

        // prefetch next step's emission
        float4 emNxt = make_float4(0.f, 0.f, 0.f, 0.f);
        if (writer && (t + 1 < TT))
            emNxt = __ldg((const float4*)&em[((b * TT + t + 1) * KK) + jW]);

        // ---- phase A: own-half i (locally produced, no wait) ----
        float a0, a1, a2, a3;
        {
            float sv = cur[rank * HALF + g];
            a0 = addx(sv, trA[0].x); a1 = addx(sv, trA[0].y);
            a2 = addx(sv, trA[0].z); a3 = addx(sv, trA[0].w);
        }
        #pragma unroll
        for (int k = 1; k < 16; ++k) {
            float sv = cur[rank * HALF + k * 8 + g];
            a0 = fmaxf(a0, addx(sv, trA[k].x));
            a1 = fmaxf(a1, addx(sv, trA[k].y));
            a2 = fmaxf(a2, addx(sv, trA[k].z));
            a3 = fmaxf(a3, addx(sv, trA[k].w));
        }

        // ---- wait for peer half of state(t-1): tx-complete mbar ----
        if (t >= 2) {
            if (nb) { mbar_wait_cluster(mb0_l, p0); p0 ^= 1u; }   // cur buf = 0
            else    { mbar_wait_cluster(mb1_l, p1); p1 ^= 1u; }   // cur buf = 1
        }

        // ---- phase B: peer-half i ----
        #pragma unroll
        for (int k = 0; k < 16; ++k) {
            float sv = cur[peer * HALF + k * 8 + g];
            a0 = fmaxf(a0, addx(sv, trB[k].x));
            a1 = fmaxf(a1, addx(sv, trB[k].y));
            a2 = fmaxf(a2, addx(sv, trB[k].z));
            a3 = fmaxf(a3, addx(sv, trB[k].w));
        }

        // butterfly max over the 8 i-groups (lane bits 2..4)
        #pragma unroll
        for (int off = 4; off <= 16; off <<= 1) {
            a0 = fmaxf(a0, __shfl_xor_sync(0xffffffffu, a0, off));
            a1 = fmaxf(a1, __shfl_xor_sync(0xffffffffu, a1, off));
            a2 = fmaxf(a2, __shfl_xor_sync(0xffffffffu, a2, off));
            a3 = fmaxf(a3, __shfl_xor_sync(0xffffffffu, a3, off));
        }

        if (writer) {
            float4 ns = make_float4(a0 + emCur.x, a1 + emCur.y,
                                    a2 + emCur.z, a3 + emCur.w);
            *(float4*)&nxt[jW] = ns;                            // local copy
            uint32_t pD = nb ? pA1 : pA0;                       // peer copy
            uint32_t pM = nb ? rmb1 : rmb0;
            st_async_b64(pD,     make_float2(ns.x, ns.y), pM);  // 8B tx each
            st_async_b64(pD + 8, make_float2(ns.z, ns.w), pM);
            *(float4*)&g_state[(t * BB + b) * KK + jW] = ns;    // for backtrace
        }
        emCur = emNxt;

        __syncthreads();   // local visibility of nxt[own half] for next phase A
    }

    // drain: consume the final phase of buffer 1 (state 1023 peer bytes) so
    // no st.async targets our SMEM after exit.
    mbar_wait_cluster(mb1_l, p1);
    cluster_sync_all();
}

// ---------------- backtrace: serial argmax recompute along decoded path -----
extern __shared__ float sT[];

__global__ void __launch_bounds__(256, 1) backtrace_kernel(float* __restrict__ out)
{
    const int b   = blockIdx.x;
    const int tid = threadIdx.x;

    for (int idx = tid; idx < SROWS * (KK / 4); idx += 256)
        ((float4*)sT)[idx] = ((const float4*)g_transT)[idx];
    __syncthreads();
    if (tid >= 32) return;
    const int lane = tid;

    // ---- last tag: argmax over state row 1023 (first-index tie-break) ----
    int cur;
    {
        const float4* rp = (const float4*)(g_state + (1023 * BB + b) * KK) + lane * 2;
        float4 sa = __ldg(rp), sb = __ldg(rp + 1);
        unsigned um = fmono(sa.x); int ui = lane * 8;
        unsigned u;
        u = fmono(sa.y); if (u > um) { um = u; ui = lane * 8 + 1; }
        u = fmono(sa.z); if (u > um) { um = u; ui = lane * 8 + 2; }
        u = fmono(sa.w); if (u > um) { um = u; ui = lane * 8 + 3; }
        u = fmono(sb.x); if (u > um) { um = u; ui = lane * 8 + 4; }
        u = fmono(sb.y); if (u > um) { um = u; ui = lane * 8 + 5; }
        u = fmono(sb.z); if (u > um) { um = u; ui = lane * 8 + 6; }
        u = fmono(sb.w); if (u > um) { um = u; ui = lane * 8 + 7; }
        unsigned gmax = __reduce_max_sync(0xffffffffu, um);
        unsigned mask = __ballot_sync(0xffffffffu, um == gmax);
        int lead = __ffs(mask) - 1;
        cur = __shfl_sync(0xffffffffu, ui, lead);
        if (lane == 0) out[b * TT + (TT - 1)] = (float)cur;
    }

    // depth-4 register prefetch of state rows (addresses independent of chain)
    float4 pfa[4], pfb[4];
    #pragma unroll
    for (int d = 0; d < 4; ++d) {
        const float4* rp = (const float4*)(g_state + ((1022 - d) * BB + b) * KK) + lane * 2;
        pfa[d] = __ldg(rp);
        pfb[d] = __ldg(rp + 1);
    }

    for (int t = TT - 1; t >= 1; --t) {
        const int slot = (TT - 1 - t) & 3;
        float4 sa = pfa[slot], sb = pfb[slot];

        int nrow = t - 5;
        if (nrow >= 0) {
            const float4* rp = (const float4*)(g_state + (nrow * BB + b) * KK) + lane * 2;
            pfa[slot] = __ldg(rp);
            pfb[slot] = __ldg(rp + 1);
        }

        const float4* trp = (cur < SROWS)
            ? (const float4*)(sT + cur * KK)
            : (const float4*)(g_transT + cur * KK);
        float4 t0 = trp[lane * 2];
        float4 t1 = trp[lane * 2 + 1];

        unsigned umA = fmono(sa.x + t0.x); int uiA = lane * 8;
        unsigned umB = fmono(sb.x + t1.x); int uiB = lane * 8 + 4;
        unsigned u;
        u = fmono(sa.y + t0.y); if (u > umA) { umA = u; uiA = lane * 8 + 1; }
        u = fmono(sb.y + t1.y); if (u > umB) { umB = u; uiB = lane * 8 + 5; }
        u = fmono(sa.z + t0.z); if (u > umA) { umA = u; uiA = lane * 8 + 2; }
        u = fmono(sb.z + t1.z); if (u > umB) { umB = u; uiB = lane * 8 + 6; }
        u = fmono(sa.w + t0.w); if (u > umA) { umA = u; uiA = lane * 8 + 3; }
        u = fmono(sb.w + t1.w); if (u > umB) { umB = u; uiB = lane * 8 + 7; }
        if (umB > umA) { umA = umB; uiA = uiB; }   // strict >: lower index wins ties

        unsigned gmax = __reduce_max_sync(0xffffffffu, umA);
        unsigned mask = __ballot_sync(0xffffffffu, umA == gmax);
        int lead = __ffs(mask) - 1;
        int prev = __shfl_sync(0xffffffffu, uiA, lead);

        if (lane == 0) out[b * TT + (t - 1)] = (float)prev;
        cur = prev;
    }
}

// ---------------- launch ----------------------------------------------------
extern "C" void kernel_launch(void* const* d_in, const int* in_sizes, int n_in,
                              void* d_out, int out_size)
{
    const float* em    = (const float*)d_in[0];  // [B, T, K] fp32
    const float* trans = (const float*)d_in[1];  // [K, K] fp32
    float* out = (float*)d_out;                  // [B, T] fp32

    const int bt_smem = SROWS * KK * (int)sizeof(float);   // 229376
    cudaFuncSetAttribute(backtrace_kernel,
                         cudaFuncAttributeMaxDynamicSharedMemorySize, bt_smem);

    transpose_kernel<<<dim3(8, 8), dim3(32, 8)>>>(trans);   // launch 1
    noop_kernel<<<1, 32>>>();                               // launch 2
    noop_kernel<<<1, 32>>>();                               // launch 3
    fwd_kernel<<<2 * BB, 256>>>(em, trans);                 // launch 4 <- ncu
    backtrace_kernel<<<BB, 256, bt_smem>>>(out);            // launch 5
}